// round 15
// baseline (speedup 1.0000x reference)
#include <cuda_runtime.h>
#include <cuda_bf16.h>
#include <cstdint>

#define N_QUBITS 10
#define DIM 1024
#define IN_F 512
#define OUT_F 64
#define BATCH 4096
#define N_LAYERS 4

typedef unsigned long long u64;

// Scratch: h = relu(x @ W_pre^T) [BATCH, DIM]
__device__ float g_h[BATCH * DIM];
// Merged diagonal phase tables per layer, per storage index: {cos, sin}
__device__ float2 g_E[N_LAYERS * DIM];
// RY coefficients per gate: {(c,c), (s,s), (-s,-s)}
__device__ u64 g_RY[N_LAYERS * N_QUBITS][3];
// bf16 split operands for the pre-GEMM
__device__ __nv_bfloat16 g_Ah[BATCH * IN_F];
__device__ __nv_bfloat16 g_Al[BATCH * IN_F];
__device__ __nv_bfloat16 g_Bh[DIM * IN_F];
__device__ __nv_bfloat16 g_Bl[DIM * IN_F];

// ---------------------------------------------------------------------------
// GF(2) linear frames for CNOT folding (all compile-time)
// ---------------------------------------------------------------------------
struct M10 { uint32_t r[10]; };

__host__ __device__ constexpr M10 frame_mat(int L) {
    M10 m{};
    for (int p = 0; p < 10; p++) m.r[p] = 1u << p;
    for (int l = 1; l <= L; l++) {
        for (int w = 0; w < 10; w++) {
            int cb = 9 - w, tb = 9 - ((w + l) % 10);
            m.r[tb] ^= m.r[cb];
        }
    }
    return m;
}

__host__ __device__ constexpr M10 mat_inv(M10 a) {
    M10 inv{};
    for (int p = 0; p < 10; p++) inv.r[p] = 1u << p;
    for (int c = 0; c < 10; c++) {
        int piv = c;
        for (int rr = c; rr < 10; rr++)
            if ((a.r[rr] >> c) & 1) { piv = rr; break; }
        uint32_t t = a.r[c]; a.r[c] = a.r[piv]; a.r[piv] = t;
        t = inv.r[c]; inv.r[c] = inv.r[piv]; inv.r[piv] = t;
        for (int rr = 0; rr < 10; rr++)
            if (rr != c && ((a.r[rr] >> c) & 1)) {
                a.r[rr] ^= a.r[c];
                inv.r[rr] ^= inv.r[c];
            }
    }
    return inv;
}

__host__ __device__ constexpr uint32_t col_mask(M10 ai, int b) {
    uint32_t v = 0;
    for (int p = 0; p < 10; p++) v |= ((ai.r[p] >> b) & 1u) << p;
    return v;
}

__host__ __device__ constexpr uint32_t msb_c(uint32_t v) {
    uint32_t r = 0;
    for (int i = 0; i < 10; i++)
        if ((v >> i) & 1) r = 1u << i;
    return r;
}

// ---------------------------------------------------------------------------
// packed f32x2 helpers
// ---------------------------------------------------------------------------
__device__ __forceinline__ u64 pk2(float lo, float hi) {
    u64 v; asm("mov.b64 %0, {%1, %2};" : "=l"(v) : "f"(lo), "f"(hi)); return v;
}
__device__ __forceinline__ void upk2(u64 v, float& lo, float& hi) {
    asm("mov.b64 {%0, %1}, %2;" : "=f"(lo), "=f"(hi) : "l"(v));
}
__device__ __forceinline__ u64 mul2(u64 a, u64 b) {
    u64 d; asm("mul.rn.f32x2 %0, %1, %2;" : "=l"(d) : "l"(a), "l"(b)); return d;
}
__device__ __forceinline__ u64 fma2(u64 a, u64 b, u64 c) {
    u64 d; asm("fma.rn.f32x2 %0, %1, %2, %3;" : "=l"(d) : "l"(a), "l"(b), "l"(c)); return d;
}
__device__ __forceinline__ uint32_t smem_u32(const void* p) {
    return (uint32_t)__cvta_generic_to_shared(p);
}
__device__ __forceinline__ void cpa16(uint32_t dst, const void* src) {
    asm volatile("cp.async.ca.shared.global [%0], [%1], 16;\n" :: "r"(dst), "l"(src));
}

// ---------------------------------------------------------------------------
// K0a: gate prep — RY coefficients + merged diagonal tables in frame form
// ---------------------------------------------------------------------------
__global__ void prep_kernel(const float* __restrict__ qw) {
    int t = blockIdx.x * 256 + threadIdx.x;   // storage index 0..1023

    uint32_t A[5][10];
    for (int p = 0; p < 10; p++) A[0][p] = 1u << p;
    for (int l = 1; l <= 4; l++) {
        for (int p = 0; p < 10; p++) A[l][p] = A[l - 1][p];
        for (int w = 0; w < 10; w++) {
            int cb = 9 - w, tb = 9 - ((w + l) % 10);
            A[l][tb] ^= A[l][cb];
        }
    }

    if (t < N_LAYERS * N_QUBITS) {
        float theta = qw[t * 3 + 1];
        float c = cosf(0.5f * theta);
        float sn = sinf(0.5f * theta);
        g_RY[t][0] = pk2(c, c);
        g_RY[t][1] = pk2(sn, sn);
        g_RY[t][2] = pk2(-sn, -sn);
    }

#pragma unroll 1
    for (int l = 0; l < N_LAYERS; l++) {
        float alpha = 0.f;
        for (int w = 0; w < N_QUBITS; w++) {
            float half = 0.5f * qw[(l * N_QUBITS + w) * 3 + 0];
            alpha += (__popc(A[l][9 - w] & (uint32_t)t) & 1) ? half : -half;
        }
        if (l > 0) {
            for (int w = 0; w < N_QUBITS; w++) {
                float half = 0.5f * qw[((l - 1) * N_QUBITS + w) * 3 + 2];
                alpha += (__popc(A[l - 1][9 - w] & (uint32_t)t) & 1) ? half : -half;
            }
        }
        float sa, ca;
        sincosf(alpha, &sa, &ca);
        g_E[l * DIM + t] = make_float2(ca, sa);
    }
}

// ---------------------------------------------------------------------------
// K0b: split x and W_pre into bf16 hi/lo
// ---------------------------------------------------------------------------
__global__ void split_kernel(const float* __restrict__ x, const float* __restrict__ w) {
    int i = blockIdx.x * 256 + threadIdx.x;
    const int AQ = (BATCH * IN_F) / 4;
    float4 v;
    __nv_bfloat16 *hd, *ld;
    int base;
    if (i < AQ) {
        v = ((const float4*)x)[i];
        hd = g_Ah; ld = g_Al; base = i * 4;
    } else {
        int j = i - AQ;
        v = ((const float4*)w)[j];
        hd = g_Bh; ld = g_Bl; base = j * 4;
    }
    float vv[4] = {v.x, v.y, v.z, v.w};
#pragma unroll
    for (int q = 0; q < 4; q++) {
        __nv_bfloat16 h = __float2bfloat16(vv[q]);
        hd[base + q] = h;
        ld[base + q] = __float2bfloat16(vv[q] - __bfloat162float(h));
    }
}

// ---------------------------------------------------------------------------
// K1: bf16-split tensor GEMM (R13 proven config: 128x64 tile, 8 warps,
// 2-stage cp.async, static smem) + row offset for batch chunking.
// ---------------------------------------------------------------------------
#define SROW 24
#define HLA (128 * SROW * 2)     // A hi->lo stride (6144)
#define STGA (2 * HLA)           // A stage stride (12288)
#define HLB (64 * SROW * 2)      // B hi->lo stride (3072)
#define STGB (2 * HLB)           // B stage stride (6144)

__device__ __forceinline__ void mma_bf16(float* c, const uint32_t* a, const uint32_t* b) {
    asm volatile(
        "mma.sync.aligned.m16n8k16.row.col.f32.bf16.bf16.f32 "
        "{%0,%1,%2,%3}, {%4,%5,%6,%7}, {%8,%9}, {%0,%1,%2,%3};\n"
        : "+f"(c[0]), "+f"(c[1]), "+f"(c[2]), "+f"(c[3])
        : "r"(a[0]), "r"(a[1]), "r"(a[2]), "r"(a[3]), "r"(b[0]), "r"(b[1]));
}
#define LDSM4(r0, r1, r2, r3, addr)                                        \
    asm volatile("ldmatrix.sync.aligned.m8n8.x4.shared.b16 {%0,%1,%2,%3}, [%4];" \
                 : "=r"(r0), "=r"(r1), "=r"(r2), "=r"(r3) : "r"(addr))

__global__ __launch_bounds__(256, 2) void gemm_bf16_kernel(
    const float* __restrict__ bias, int bm0) {
    __shared__ __nv_bfloat16 sA[2][2][128][SROW];   // 24 KB
    __shared__ __nv_bfloat16 sB[2][2][64][SROW];    // 12 KB

    int tid = threadIdx.x;
    int lane = tid & 31;
    int w = tid >> 5;            // 0..7
    int wm = w >> 1;             // 0..3 -> 32-row slab
    int wn = w & 1;              // 0..1 -> 32-col slab
    int gr = lane >> 2;
    int gc = lane & 3;
    int bm = bm0 + blockIdx.y * 128;
    int bn = blockIdx.x * 64;

    float acc[2][4][4];
#pragma unroll
    for (int mi = 0; mi < 2; mi++)
#pragma unroll
        for (int ni = 0; ni < 4; ni++)
#pragma unroll
            for (int q = 0; q < 4; q++) acc[mi][ni][q] = 0.f;

    int sa0 = tid, sa1 = tid + 256;
    int ha0 = sa0 >> 8, ra0 = (sa0 & 255) >> 1, ca0 = sa0 & 1;
    int ha1 = sa1 >> 8, ra1 = (sa1 & 255) >> 1, ca1 = sa1 & 1;
    int hb = tid >> 7, rb = (tid & 127) >> 1, cb = tid & 1;

    const __nv_bfloat16* gA0 = (ha0 ? g_Al : g_Ah) + (size_t)(bm + ra0) * IN_F + ca0 * 8;
    const __nv_bfloat16* gA1 = (ha1 ? g_Al : g_Ah) + (size_t)(bm + ra1) * IN_F + ca1 * 8;
    const __nv_bfloat16* gB  = (hb ? g_Bl : g_Bh) + (size_t)(bn + rb) * IN_F + cb * 8;
    uint32_t dA0 = smem_u32(&sA[0][ha0][ra0][0]) + (uint32_t)ca0 * 16;
    uint32_t dA1 = smem_u32(&sA[0][ha1][ra1][0]) + (uint32_t)ca1 * 16;
    uint32_t dB  = smem_u32(&sB[0][hb][rb][0]) + (uint32_t)cb * 16;

    int arow = ((lane >> 3) & 1) * 8 + (lane & 7);
    int acol = (lane >> 4) * 8;
    uint32_t aoff = (uint32_t)(arow * SROW + acol) * 2;
    int brow = ((lane >> 4) & 1) * 8 + (lane & 7);
    int bcol = ((lane >> 3) & 1) * 8;
    uint32_t boff = (uint32_t)(brow * SROW + bcol) * 2;

    uint32_t sA_base = smem_u32(&sA[0][0][0][0]);
    uint32_t sB_base = smem_u32(&sB[0][0][0][0]);

    const int NK = IN_F / 16;   // 32

    cpa16(dA0, gA0);
    cpa16(dA1, gA1);
    cpa16(dB, gB);
    asm volatile("cp.async.commit_group;\n");

    for (int k = 0; k < NK; k++) {
        int buf = k & 1;
        asm volatile("cp.async.wait_group 0;\n");
        __syncthreads();
        if (k + 1 < NK) {
            uint32_t soa = (uint32_t)((k + 1) & 1) * STGA;
            uint32_t sob = (uint32_t)((k + 1) & 1) * STGB;
            cpa16(dA0 + soa, gA0 + (k + 1) * 16);
            cpa16(dA1 + soa, gA1 + (k + 1) * 16);
            cpa16(dB + sob, gB + (k + 1) * 16);
            asm volatile("cp.async.commit_group;\n");
        }

        uint32_t bh[4][2], bl[4][2];
#pragma unroll
        for (int p = 0; p < 2; p++) {
            uint32_t base = sB_base + (uint32_t)buf * STGB +
                            (uint32_t)(wn * 32 + p * 16) * (SROW * 2) + boff;
            uint32_t r0, r1, r2, r3;
            LDSM4(r0, r1, r2, r3, base);
            bh[2 * p][0] = r0; bh[2 * p][1] = r1;
            bh[2 * p + 1][0] = r2; bh[2 * p + 1][1] = r3;
            LDSM4(r0, r1, r2, r3, base + HLB);
            bl[2 * p][0] = r0; bl[2 * p][1] = r1;
            bl[2 * p + 1][0] = r2; bl[2 * p + 1][1] = r3;
        }

#pragma unroll
        for (int mi = 0; mi < 2; mi++) {
            uint32_t base = sA_base + (uint32_t)buf * STGA +
                            (uint32_t)(wm * 32 + mi * 16) * (SROW * 2) + aoff;
            uint32_t ah[4], al[4];
            LDSM4(ah[0], ah[1], ah[2], ah[3], base);
            LDSM4(al[0], al[1], al[2], al[3], base + HLA);
#pragma unroll
            for (int ni = 0; ni < 4; ni++) {
                mma_bf16(acc[mi][ni], ah, bh[ni]);
                mma_bf16(acc[mi][ni], ah, bl[ni]);
                mma_bf16(acc[mi][ni], al, bh[ni]);
            }
        }
    }

    float bv[4][2];
#pragma unroll
    for (int ni = 0; ni < 4; ni++) {
        int col0 = bn + wn * 32 + ni * 8 + gc * 2;
        bv[ni][0] = bias[col0];
        bv[ni][1] = bias[col0 + 1];
    }
#pragma unroll
    for (int mi = 0; mi < 2; mi++) {
        int row0 = bm + wm * 32 + mi * 16 + gr;
#pragma unroll
        for (int ni = 0; ni < 4; ni++) {
            int col0 = bn + wn * 32 + ni * 8 + gc * 2;
            float v0 = acc[mi][ni][0] + bv[ni][0];
            float v1 = acc[mi][ni][1] + bv[ni][1];
            float v2 = acc[mi][ni][2] + bv[ni][0];
            float v3 = acc[mi][ni][3] + bv[ni][1];
            v0 = v0 > 0.f ? v0 : 0.f;
            v1 = v1 > 0.f ? v1 : 0.f;
            v2 = v2 > 0.f ? v2 : 0.f;
            v3 = v3 > 0.f ? v3 : 0.f;
            *(float2*)&g_h[(size_t)row0 * DIM + col0] = make_float2(v0, v1);
            *(float2*)&g_h[(size_t)(row0 + 8) * DIM + col0] = make_float2(v2, v3);
        }
    }
}

// ---------------------------------------------------------------------------
// K2: warp-per-row register statevector with CNOT folding (R13 engine,
// + batch offset for chunking)
// ---------------------------------------------------------------------------
__device__ __forceinline__ u64 swap_halves(u64 v) {
    float lo, hi; upk2(v, lo, hi);
    return pk2(hi, lo);
}

__device__ __forceinline__ void apply_diag(u64* s, const float2* __restrict__ tab,
                                           int lane) {
#pragma unroll
    for (int j = 0; j < 32; j++) {
        float2 e = tab[j * 32 + lane];
        u64 c2 = pk2(e.x, e.x);
        u64 ms = pk2(-e.y, e.y);
        u64 sw = swap_halves(s[j]);
        s[j] = fma2(ms, sw, mul2(c2, s[j]));
    }
}

template<uint32_t V, uint32_t U>
__device__ __forceinline__ void ry_gen(u64* s, u64 c2, u64 sp, u64 sn, int lane) {
    constexpr uint32_t VJ = (V >> 5) & 31u;
    constexpr uint32_t VL = V & 31u;
    constexpr uint32_t UJ = (U >> 5) & 31u;
    constexpr uint32_t UL = U & 31u;
    bool lp = UL ? ((__popc(lane & (int)UL) & 1) != 0) : false;
    u64 cA = lp ? sn : sp;
    u64 cB = lp ? sp : sn;

    if constexpr (VL == 0) {
        constexpr uint32_t MSB = msb_c(VJ);
#pragma unroll
        for (int j = 0; j < 32; j++) {
            if ((j & (int)MSB) == 0) {
                int j1 = j ^ (int)VJ;
                u64 a = s[j], b = s[j1];
                bool cj = (__popc(j & (int)UJ) & 1) != 0;
                bool cj1 = (__popc(j1 & (int)UJ) & 1) != 0;
                s[j]  = fma2(cj  ? cA : cB, b, mul2(c2, a));
                s[j1] = fma2(cj1 ? cA : cB, a, mul2(c2, b));
            }
        }
    } else if constexpr (VJ == 0) {
#pragma unroll
        for (int j = 0; j < 32; j++) {
            u64 p = __shfl_xor_sync(0xffffffffu, s[j], (int)VL);
            bool cj = (__popc(j & (int)UJ) & 1) != 0;
            s[j] = fma2(cj ? cA : cB, p, mul2(c2, s[j]));
        }
    } else {
        constexpr uint32_t MSB = msb_c(VJ);
#pragma unroll
        for (int j = 0; j < 32; j++) {
            if ((j & (int)MSB) == 0) {
                int j1 = j ^ (int)VJ;
                u64 pa = __shfl_xor_sync(0xffffffffu, s[j1], (int)VL);
                u64 pb = __shfl_xor_sync(0xffffffffu, s[j], (int)VL);
                bool cj = (__popc(j & (int)UJ) & 1) != 0;
                bool cj1 = (__popc(j1 & (int)UJ) & 1) != 0;
                s[j]  = fma2(cj  ? cA : cB, pa, mul2(c2, s[j]));
                s[j1] = fma2(cj1 ? cA : cB, pb, mul2(c2, s[j1]));
            }
        }
    }
}

template<int L, int W>
__device__ __forceinline__ void ry_layer(u64* s, int lane) {
    if constexpr (W < N_QUBITS) {
        constexpr M10 A = frame_mat(L);
        constexpr M10 AI = mat_inv(frame_mat(L));
        constexpr uint32_t V = col_mask(AI, 9 - W);
        constexpr uint32_t U = A.r[9 - W];
        const u64* R = &g_RY[L * N_QUBITS + W][0];
        ry_gen<V, U>(s, R[0], R[1], R[2], lane);
        ry_layer<L, W + 1>(s, lane);
    }
}

__global__ __launch_bounds__(256, 2) void quantum_reg_kernel(
    const float* __restrict__ W_post, const float* __restrict__ b_post,
    float* __restrict__ out, int b0) {
    int lane = threadIdx.x & 31;
    int b = b0 + blockIdx.x * 8 + (threadIdx.x >> 5);

    u64 s[32];
    const float* hrow = g_h + (size_t)b * DIM;
#pragma unroll
    for (int j = 0; j < 32; j++) {
        float v = hrow[j * 32 + lane];
        s[j] = pk2(v, 0.f);
    }

    apply_diag(s, g_E + 0 * DIM, lane);
    ry_layer<0, 0>(s, lane);
    apply_diag(s, g_E + 1 * DIM, lane);
    ry_layer<1, 0>(s, lane);
    apply_diag(s, g_E + 2 * DIM, lane);
    ry_layer<2, 0>(s, lane);
    apply_diag(s, g_E + 3 * DIM, lane);
    ry_layer<3, 0>(s, lane);

    constexpr M10 A4 = frame_mat(4);
    float S = 0.f;
    float za[N_QUBITS];
#pragma unroll
    for (int w = 0; w < N_QUBITS; w++) za[w] = 0.f;
#pragma unroll
    for (int j = 0; j < 32; j++) {
        float ar, ai;
        upk2(s[j], ar, ai);
        float p = ar * ar + ai * ai;
        S += p;
#pragma unroll
        for (int w = 0; w < N_QUBITS; w++) {
            int uj = (int)((A4.r[9 - w] >> 5) & 31u);
            za[w] += (__popc(j & uj) & 1) ? -p : p;
        }
    }
#pragma unroll
    for (int w = 0; w < N_QUBITS; w++) {
        int ul = (int)(A4.r[9 - w] & 31u);
        if (__popc(lane & ul) & 1) za[w] = -za[w];
    }

    float n2 = S;
#pragma unroll
    for (int o = 16; o; o >>= 1) {
        n2 += __shfl_xor_sync(0xffffffffu, n2, o);
#pragma unroll
        for (int w = 0; w < N_QUBITS; w++)
            za[w] += __shfl_xor_sync(0xffffffffu, za[w], o);
    }
    float inv = 1.f / n2;
#pragma unroll
    for (int w = 0; w < N_QUBITS; w++) za[w] *= inv;

#pragma unroll
    for (int oo = 0; oo < 2; oo++) {
        int o = lane + 32 * oo;
        float acc = b_post[o];
#pragma unroll
        for (int w = 0; w < N_QUBITS; w++)
            acc += za[w] * W_post[o * N_QUBITS + w];
        out[(size_t)b * OUT_F + o] = acc;
    }
}

// ---------------------------------------------------------------------------
// Launch: 4-way chunked software pipeline across two streams.
// s0: split -> g0 -> g1 -> g2 -> g3     (GEMM = tensor-pipe bound)
// s1: prep -> q0..q3 (each after its GEMM chunk; MIO/FMA bound)
// ---------------------------------------------------------------------------
#define NCHUNK 4
#define CHUNK (BATCH / NCHUNK)   // 1024 rows

extern "C" void kernel_launch(void* const* d_in, const int* in_sizes, int n_in,
                              void* d_out, int out_size) {
    const float* x      = (const float*)d_in[0];
    const float* W_pre  = (const float*)d_in[1];
    const float* b_pre  = (const float*)d_in[2];
    const float* qw     = (const float*)d_in[3];
    const float* W_post = (const float*)d_in[4];
    const float* b_post = (const float*)d_in[5];
    float* out = (float*)d_out;

    static cudaStream_t s2 = nullptr;
    static cudaEvent_t evFork, evJoin, evG[NCHUNK];
    if (!s2) {
        cudaStreamCreateWithFlags(&s2, cudaStreamNonBlocking);
        cudaEventCreateWithFlags(&evFork, cudaEventDisableTiming);
        cudaEventCreateWithFlags(&evJoin, cudaEventDisableTiming);
        for (int i = 0; i < NCHUNK; i++)
            cudaEventCreateWithFlags(&evG[i], cudaEventDisableTiming);
    }

    // fork side stream; prep runs beside split/gemm
    cudaEventRecord(evFork, 0);
    cudaStreamWaitEvent(s2, evFork, 0);
    prep_kernel<<<4, 256, 0, s2>>>(qw);

    split_kernel<<<(BATCH * IN_F + DIM * IN_F) / 4 / 256, 256>>>(x, W_pre);

    dim3 gg(DIM / 64, CHUNK / 128);
    for (int i = 0; i < NCHUNK; i++) {
        gemm_bf16_kernel<<<gg, 256>>>(b_pre, i * CHUNK);
        cudaEventRecord(evG[i], 0);
        cudaStreamWaitEvent(s2, evG[i], 0);
        quantum_reg_kernel<<<CHUNK / 8, 256, 0, s2>>>(W_post, b_post, out, i * CHUNK);
    }

    cudaEventRecord(evJoin, s2);
    cudaStreamWaitEvent(0, evJoin, 0);
}

// round 16
// speedup vs baseline: 1.1990x; 1.1990x over previous
#include <cuda_runtime.h>
#include <cuda_bf16.h>
#include <cstdint>

#define N_QUBITS 10
#define DIM 1024
#define IN_F 512
#define OUT_F 64
#define BATCH 4096
#define N_LAYERS 4

typedef unsigned long long u64;

// Scratch: h = relu(x @ W_pre^T) [BATCH, DIM]
__device__ float g_h[BATCH * DIM];
// Merged diagonal phase tables per layer, per storage index: {cos, sin}
__device__ float2 g_E[N_LAYERS * DIM];
// RY coefficients per gate: {(c,c), (s,s), (-s,-s)}
__device__ u64 g_RY[N_LAYERS * N_QUBITS][3];
// bf16 split operands for the pre-GEMM
__device__ __nv_bfloat16 g_Ah[BATCH * IN_F];
__device__ __nv_bfloat16 g_Al[BATCH * IN_F];
__device__ __nv_bfloat16 g_Bh[DIM * IN_F];
__device__ __nv_bfloat16 g_Bl[DIM * IN_F];

// ---------------------------------------------------------------------------
// GF(2) linear frames for CNOT folding (all compile-time)
// ---------------------------------------------------------------------------
struct M10 { uint32_t r[10]; };

__host__ __device__ constexpr M10 frame_mat(int L) {
    M10 m{};
    for (int p = 0; p < 10; p++) m.r[p] = 1u << p;
    for (int l = 1; l <= L; l++) {
        for (int w = 0; w < 10; w++) {
            int cb = 9 - w, tb = 9 - ((w + l) % 10);
            m.r[tb] ^= m.r[cb];
        }
    }
    return m;
}

__host__ __device__ constexpr M10 mat_inv(M10 a) {
    M10 inv{};
    for (int p = 0; p < 10; p++) inv.r[p] = 1u << p;
    for (int c = 0; c < 10; c++) {
        int piv = c;
        for (int rr = c; rr < 10; rr++)
            if ((a.r[rr] >> c) & 1) { piv = rr; break; }
        uint32_t t = a.r[c]; a.r[c] = a.r[piv]; a.r[piv] = t;
        t = inv.r[c]; inv.r[c] = inv.r[piv]; inv.r[piv] = t;
        for (int rr = 0; rr < 10; rr++)
            if (rr != c && ((a.r[rr] >> c) & 1)) {
                a.r[rr] ^= a.r[c];
                inv.r[rr] ^= inv.r[c];
            }
    }
    return inv;
}

__host__ __device__ constexpr uint32_t col_mask(M10 ai, int b) {
    uint32_t v = 0;
    for (int p = 0; p < 10; p++) v |= ((ai.r[p] >> b) & 1u) << p;
    return v;
}

__host__ __device__ constexpr uint32_t msb_c(uint32_t v) {
    uint32_t r = 0;
    for (int i = 0; i < 10; i++)
        if ((v >> i) & 1) r = 1u << i;
    return r;
}

// ---------------------------------------------------------------------------
// packed f32x2 helpers
// ---------------------------------------------------------------------------
__device__ __forceinline__ u64 pk2(float lo, float hi) {
    u64 v; asm("mov.b64 %0, {%1, %2};" : "=l"(v) : "f"(lo), "f"(hi)); return v;
}
__device__ __forceinline__ void upk2(u64 v, float& lo, float& hi) {
    asm("mov.b64 {%0, %1}, %2;" : "=f"(lo), "=f"(hi) : "l"(v));
}
__device__ __forceinline__ u64 mul2(u64 a, u64 b) {
    u64 d; asm("mul.rn.f32x2 %0, %1, %2;" : "=l"(d) : "l"(a), "l"(b)); return d;
}
__device__ __forceinline__ u64 fma2(u64 a, u64 b, u64 c) {
    u64 d; asm("fma.rn.f32x2 %0, %1, %2, %3;" : "=l"(d) : "l"(a), "l"(b), "l"(c)); return d;
}
__device__ __forceinline__ uint32_t smem_u32(const void* p) {
    return (uint32_t)__cvta_generic_to_shared(p);
}
__device__ __forceinline__ void cpa16(uint32_t dst, const void* src) {
    asm volatile("cp.async.ca.shared.global [%0], [%1], 16;\n" :: "r"(dst), "l"(src));
}

// ---------------------------------------------------------------------------
// K0a: gate prep — RY coefficients + merged diagonal tables in frame form
// ---------------------------------------------------------------------------
__global__ void prep_kernel(const float* __restrict__ qw) {
    int t = blockIdx.x * 256 + threadIdx.x;   // storage index 0..1023

    uint32_t A[5][10];
    for (int p = 0; p < 10; p++) A[0][p] = 1u << p;
    for (int l = 1; l <= 4; l++) {
        for (int p = 0; p < 10; p++) A[l][p] = A[l - 1][p];
        for (int w = 0; w < 10; w++) {
            int cb = 9 - w, tb = 9 - ((w + l) % 10);
            A[l][tb] ^= A[l][cb];
        }
    }

    if (t < N_LAYERS * N_QUBITS) {
        float theta = qw[t * 3 + 1];
        float c = cosf(0.5f * theta);
        float sn = sinf(0.5f * theta);
        g_RY[t][0] = pk2(c, c);
        g_RY[t][1] = pk2(sn, sn);
        g_RY[t][2] = pk2(-sn, -sn);
    }

#pragma unroll 1
    for (int l = 0; l < N_LAYERS; l++) {
        float alpha = 0.f;
        for (int w = 0; w < N_QUBITS; w++) {
            float half = 0.5f * qw[(l * N_QUBITS + w) * 3 + 0];
            alpha += (__popc(A[l][9 - w] & (uint32_t)t) & 1) ? half : -half;
        }
        if (l > 0) {
            for (int w = 0; w < N_QUBITS; w++) {
                float half = 0.5f * qw[((l - 1) * N_QUBITS + w) * 3 + 2];
                alpha += (__popc(A[l - 1][9 - w] & (uint32_t)t) & 1) ? half : -half;
            }
        }
        float sa, ca;
        sincosf(alpha, &sa, &ca);
        g_E[l * DIM + t] = make_float2(ca, sa);
    }
}

// ---------------------------------------------------------------------------
// K0b: split x and W_pre into bf16 hi/lo
// ---------------------------------------------------------------------------
__global__ void split_kernel(const float* __restrict__ x, const float* __restrict__ w) {
    int i = blockIdx.x * 256 + threadIdx.x;
    const int AQ = (BATCH * IN_F) / 4;
    float4 v;
    __nv_bfloat16 *hd, *ld;
    int base;
    if (i < AQ) {
        v = ((const float4*)x)[i];
        hd = g_Ah; ld = g_Al; base = i * 4;
    } else {
        int j = i - AQ;
        v = ((const float4*)w)[j];
        hd = g_Bh; ld = g_Bl; base = j * 4;
    }
    float vv[4] = {v.x, v.y, v.z, v.w};
#pragma unroll
    for (int q = 0; q < 4; q++) {
        __nv_bfloat16 h = __float2bfloat16(vv[q]);
        hd[base + q] = h;
        ld[base + q] = __float2bfloat16(vv[q] - __bfloat162float(h));
    }
}

// ---------------------------------------------------------------------------
// K1: bf16-split tensor GEMM (R12/best config: 128x64 tile, 8 warps,
// 2-stage cp.async, static smem, serial full-batch launch)
// ---------------------------------------------------------------------------
#define SROW 24
#define HLA (128 * SROW * 2)     // A hi->lo stride (6144)
#define STGA (2 * HLA)           // A stage stride (12288)
#define HLB (64 * SROW * 2)      // B hi->lo stride (3072)
#define STGB (2 * HLB)           // B stage stride (6144)

__device__ __forceinline__ void mma_bf16(float* c, const uint32_t* a, const uint32_t* b) {
    asm volatile(
        "mma.sync.aligned.m16n8k16.row.col.f32.bf16.bf16.f32 "
        "{%0,%1,%2,%3}, {%4,%5,%6,%7}, {%8,%9}, {%0,%1,%2,%3};\n"
        : "+f"(c[0]), "+f"(c[1]), "+f"(c[2]), "+f"(c[3])
        : "r"(a[0]), "r"(a[1]), "r"(a[2]), "r"(a[3]), "r"(b[0]), "r"(b[1]));
}
#define LDSM4(r0, r1, r2, r3, addr)                                        \
    asm volatile("ldmatrix.sync.aligned.m8n8.x4.shared.b16 {%0,%1,%2,%3}, [%4];" \
                 : "=r"(r0), "=r"(r1), "=r"(r2), "=r"(r3) : "r"(addr))

__global__ __launch_bounds__(256, 2) void gemm_bf16_kernel(const float* __restrict__ bias) {
    __shared__ __nv_bfloat16 sA[2][2][128][SROW];   // 24 KB
    __shared__ __nv_bfloat16 sB[2][2][64][SROW];    // 12 KB

    int tid = threadIdx.x;
    int lane = tid & 31;
    int w = tid >> 5;            // 0..7
    int wm = w >> 1;             // 0..3 -> 32-row slab
    int wn = w & 1;              // 0..1 -> 32-col slab
    int gr = lane >> 2;
    int gc = lane & 3;
    int bm = blockIdx.y * 128;
    int bn = blockIdx.x * 64;

    float acc[2][4][4];
#pragma unroll
    for (int mi = 0; mi < 2; mi++)
#pragma unroll
        for (int ni = 0; ni < 4; ni++)
#pragma unroll
            for (int q = 0; q < 4; q++) acc[mi][ni][q] = 0.f;

    int sa0 = tid, sa1 = tid + 256;
    int ha0 = sa0 >> 8, ra0 = (sa0 & 255) >> 1, ca0 = sa0 & 1;
    int ha1 = sa1 >> 8, ra1 = (sa1 & 255) >> 1, ca1 = sa1 & 1;
    int hb = tid >> 7, rb = (tid & 127) >> 1, cb = tid & 1;

    const __nv_bfloat16* gA0 = (ha0 ? g_Al : g_Ah) + (size_t)(bm + ra0) * IN_F + ca0 * 8;
    const __nv_bfloat16* gA1 = (ha1 ? g_Al : g_Ah) + (size_t)(bm + ra1) * IN_F + ca1 * 8;
    const __nv_bfloat16* gB  = (hb ? g_Bl : g_Bh) + (size_t)(bn + rb) * IN_F + cb * 8;
    uint32_t dA0 = smem_u32(&sA[0][ha0][ra0][0]) + (uint32_t)ca0 * 16;
    uint32_t dA1 = smem_u32(&sA[0][ha1][ra1][0]) + (uint32_t)ca1 * 16;
    uint32_t dB  = smem_u32(&sB[0][hb][rb][0]) + (uint32_t)cb * 16;

    int arow = ((lane >> 3) & 1) * 8 + (lane & 7);
    int acol = (lane >> 4) * 8;
    uint32_t aoff = (uint32_t)(arow * SROW + acol) * 2;
    int brow = ((lane >> 4) & 1) * 8 + (lane & 7);
    int bcol = ((lane >> 3) & 1) * 8;
    uint32_t boff = (uint32_t)(brow * SROW + bcol) * 2;

    uint32_t sA_base = smem_u32(&sA[0][0][0][0]);
    uint32_t sB_base = smem_u32(&sB[0][0][0][0]);

    const int NK = IN_F / 16;   // 32

    cpa16(dA0, gA0);
    cpa16(dA1, gA1);
    cpa16(dB, gB);
    asm volatile("cp.async.commit_group;\n");

    for (int k = 0; k < NK; k++) {
        int buf = k & 1;
        asm volatile("cp.async.wait_group 0;\n");
        __syncthreads();
        if (k + 1 < NK) {
            uint32_t soa = (uint32_t)((k + 1) & 1) * STGA;
            uint32_t sob = (uint32_t)((k + 1) & 1) * STGB;
            cpa16(dA0 + soa, gA0 + (k + 1) * 16);
            cpa16(dA1 + soa, gA1 + (k + 1) * 16);
            cpa16(dB + sob, gB + (k + 1) * 16);
            asm volatile("cp.async.commit_group;\n");
        }

        uint32_t bh[4][2], bl[4][2];
#pragma unroll
        for (int p = 0; p < 2; p++) {
            uint32_t base = sB_base + (uint32_t)buf * STGB +
                            (uint32_t)(wn * 32 + p * 16) * (SROW * 2) + boff;
            uint32_t r0, r1, r2, r3;
            LDSM4(r0, r1, r2, r3, base);
            bh[2 * p][0] = r0; bh[2 * p][1] = r1;
            bh[2 * p + 1][0] = r2; bh[2 * p + 1][1] = r3;
            LDSM4(r0, r1, r2, r3, base + HLB);
            bl[2 * p][0] = r0; bl[2 * p][1] = r1;
            bl[2 * p + 1][0] = r2; bl[2 * p + 1][1] = r3;
        }

#pragma unroll
        for (int mi = 0; mi < 2; mi++) {
            uint32_t base = sA_base + (uint32_t)buf * STGA +
                            (uint32_t)(wm * 32 + mi * 16) * (SROW * 2) + aoff;
            uint32_t ah[4], al[4];
            LDSM4(ah[0], ah[1], ah[2], ah[3], base);
            LDSM4(al[0], al[1], al[2], al[3], base + HLA);
#pragma unroll
            for (int ni = 0; ni < 4; ni++) {
                mma_bf16(acc[mi][ni], ah, bh[ni]);
                mma_bf16(acc[mi][ni], ah, bl[ni]);
                mma_bf16(acc[mi][ni], al, bh[ni]);
            }
        }
    }

    float bv[4][2];
#pragma unroll
    for (int ni = 0; ni < 4; ni++) {
        int col0 = bn + wn * 32 + ni * 8 + gc * 2;
        bv[ni][0] = bias[col0];
        bv[ni][1] = bias[col0 + 1];
    }
#pragma unroll
    for (int mi = 0; mi < 2; mi++) {
        int row0 = bm + wm * 32 + mi * 16 + gr;
#pragma unroll
        for (int ni = 0; ni < 4; ni++) {
            int col0 = bn + wn * 32 + ni * 8 + gc * 2;
            float v0 = acc[mi][ni][0] + bv[ni][0];
            float v1 = acc[mi][ni][1] + bv[ni][1];
            float v2 = acc[mi][ni][2] + bv[ni][0];
            float v3 = acc[mi][ni][3] + bv[ni][1];
            v0 = v0 > 0.f ? v0 : 0.f;
            v1 = v1 > 0.f ? v1 : 0.f;
            v2 = v2 > 0.f ? v2 : 0.f;
            v3 = v3 > 0.f ? v3 : 0.f;
            *(float2*)&g_h[(size_t)row0 * DIM + col0] = make_float2(v0, v1);
            *(float2*)&g_h[(size_t)(row0 + 8) * DIM + col0] = make_float2(v2, v3);
        }
    }
}

// ---------------------------------------------------------------------------
// K2: warp-per-row register statevector with CNOT folding.
// NEW: 128-thread CTAs + __launch_bounds__(128,5) to cap regs (~102) and
// raise resident warps/SM 16 -> ~20. Layer-0 diagonal fused into the load
// (input is real: s = (v*cos, v*sin)).
// ---------------------------------------------------------------------------
__device__ __forceinline__ u64 swap_halves(u64 v) {
    float lo, hi; upk2(v, lo, hi);
    return pk2(hi, lo);
}

__device__ __forceinline__ void apply_diag(u64* s, const float2* __restrict__ tab,
                                           int lane) {
#pragma unroll
    for (int j = 0; j < 32; j++) {
        float2 e = tab[j * 32 + lane];
        u64 c2 = pk2(e.x, e.x);
        u64 ms = pk2(-e.y, e.y);
        u64 sw = swap_halves(s[j]);
        s[j] = fma2(ms, sw, mul2(c2, s[j]));
    }
}

template<uint32_t V, uint32_t U>
__device__ __forceinline__ void ry_gen(u64* s, u64 c2, u64 sp, u64 sn, int lane) {
    constexpr uint32_t VJ = (V >> 5) & 31u;
    constexpr uint32_t VL = V & 31u;
    constexpr uint32_t UJ = (U >> 5) & 31u;
    constexpr uint32_t UL = U & 31u;
    bool lp = UL ? ((__popc(lane & (int)UL) & 1) != 0) : false;
    u64 cA = lp ? sn : sp;
    u64 cB = lp ? sp : sn;

    if constexpr (VL == 0) {
        constexpr uint32_t MSB = msb_c(VJ);
#pragma unroll
        for (int j = 0; j < 32; j++) {
            if ((j & (int)MSB) == 0) {
                int j1 = j ^ (int)VJ;
                u64 a = s[j], b = s[j1];
                bool cj = (__popc(j & (int)UJ) & 1) != 0;
                bool cj1 = (__popc(j1 & (int)UJ) & 1) != 0;
                s[j]  = fma2(cj  ? cA : cB, b, mul2(c2, a));
                s[j1] = fma2(cj1 ? cA : cB, a, mul2(c2, b));
            }
        }
    } else if constexpr (VJ == 0) {
#pragma unroll
        for (int j = 0; j < 32; j++) {
            u64 p = __shfl_xor_sync(0xffffffffu, s[j], (int)VL);
            bool cj = (__popc(j & (int)UJ) & 1) != 0;
            s[j] = fma2(cj ? cA : cB, p, mul2(c2, s[j]));
        }
    } else {
        constexpr uint32_t MSB = msb_c(VJ);
#pragma unroll
        for (int j = 0; j < 32; j++) {
            if ((j & (int)MSB) == 0) {
                int j1 = j ^ (int)VJ;
                u64 pa = __shfl_xor_sync(0xffffffffu, s[j1], (int)VL);
                u64 pb = __shfl_xor_sync(0xffffffffu, s[j], (int)VL);
                bool cj = (__popc(j & (int)UJ) & 1) != 0;
                bool cj1 = (__popc(j1 & (int)UJ) & 1) != 0;
                s[j]  = fma2(cj  ? cA : cB, pa, mul2(c2, s[j]));
                s[j1] = fma2(cj1 ? cA : cB, pb, mul2(c2, s[j1]));
            }
        }
    }
}

template<int L, int W>
__device__ __forceinline__ void ry_layer(u64* s, int lane) {
    if constexpr (W < N_QUBITS) {
        constexpr M10 A = frame_mat(L);
        constexpr M10 AI = mat_inv(frame_mat(L));
        constexpr uint32_t V = col_mask(AI, 9 - W);
        constexpr uint32_t U = A.r[9 - W];
        const u64* R = &g_RY[L * N_QUBITS + W][0];
        ry_gen<V, U>(s, R[0], R[1], R[2], lane);
        ry_layer<L, W + 1>(s, lane);
    }
}

__global__ __launch_bounds__(128, 5) void quantum_reg_kernel(
    const float* __restrict__ W_post, const float* __restrict__ b_post,
    float* __restrict__ out) {
    int lane = threadIdx.x & 31;
    int b = blockIdx.x * 4 + (threadIdx.x >> 5);

    u64 s[32];
    const float* hrow = g_h + (size_t)b * DIM;
    const float2* tab0 = g_E;           // layer 0 diagonal, fused with load
#pragma unroll
    for (int j = 0; j < 32; j++) {
        float v = hrow[j * 32 + lane];
        float2 e = tab0[j * 32 + lane];
        s[j] = pk2(v * e.x, v * e.y);   // real input: diag0 applied directly
    }

    ry_layer<0, 0>(s, lane);
    apply_diag(s, g_E + 1 * DIM, lane);
    ry_layer<1, 0>(s, lane);
    apply_diag(s, g_E + 2 * DIM, lane);
    ry_layer<2, 0>(s, lane);
    apply_diag(s, g_E + 3 * DIM, lane);
    ry_layer<3, 0>(s, lane);

    constexpr M10 A4 = frame_mat(4);
    float S = 0.f;
    float za[N_QUBITS];
#pragma unroll
    for (int w = 0; w < N_QUBITS; w++) za[w] = 0.f;
#pragma unroll
    for (int j = 0; j < 32; j++) {
        float ar, ai;
        upk2(s[j], ar, ai);
        float p = ar * ar + ai * ai;
        S += p;
#pragma unroll
        for (int w = 0; w < N_QUBITS; w++) {
            int uj = (int)((A4.r[9 - w] >> 5) & 31u);
            za[w] += (__popc(j & uj) & 1) ? -p : p;
        }
    }
#pragma unroll
    for (int w = 0; w < N_QUBITS; w++) {
        int ul = (int)(A4.r[9 - w] & 31u);
        if (__popc(lane & ul) & 1) za[w] = -za[w];
    }

    float n2 = S;
#pragma unroll
    for (int o = 16; o; o >>= 1) {
        n2 += __shfl_xor_sync(0xffffffffu, n2, o);
#pragma unroll
        for (int w = 0; w < N_QUBITS; w++)
            za[w] += __shfl_xor_sync(0xffffffffu, za[w], o);
    }
    float inv = 1.f / n2;
#pragma unroll
    for (int w = 0; w < N_QUBITS; w++) za[w] *= inv;

#pragma unroll
    for (int oo = 0; oo < 2; oo++) {
        int o = lane + 32 * oo;
        float acc = b_post[o];
#pragma unroll
        for (int w = 0; w < N_QUBITS; w++)
            acc += za[w] * W_post[o * N_QUBITS + w];
        out[(size_t)b * OUT_F + o] = acc;
    }
}

// ---------------------------------------------------------------------------
// Launch: prep on side stream (hidden under split+GEMM); serial otherwise.
// ---------------------------------------------------------------------------
extern "C" void kernel_launch(void* const* d_in, const int* in_sizes, int n_in,
                              void* d_out, int out_size) {
    const float* x      = (const float*)d_in[0];
    const float* W_pre  = (const float*)d_in[1];
    const float* b_pre  = (const float*)d_in[2];
    const float* qw     = (const float*)d_in[3];
    const float* W_post = (const float*)d_in[4];
    const float* b_post = (const float*)d_in[5];
    float* out = (float*)d_out;

    static cudaStream_t s2 = nullptr;
    static cudaEvent_t evFork, evJoin;
    if (!s2) {
        cudaStreamCreateWithFlags(&s2, cudaStreamNonBlocking);
        cudaEventCreateWithFlags(&evFork, cudaEventDisableTiming);
        cudaEventCreateWithFlags(&evJoin, cudaEventDisableTiming);
    }

    cudaEventRecord(evFork, 0);
    cudaStreamWaitEvent(s2, evFork, 0);
    prep_kernel<<<4, 256, 0, s2>>>(qw);
    cudaEventRecord(evJoin, s2);

    split_kernel<<<(BATCH * IN_F + DIM * IN_F) / 4 / 256, 256>>>(x, W_pre);

    dim3 g1(DIM / 64, BATCH / 128);
    gemm_bf16_kernel<<<g1, 256>>>(b_pre);

    cudaStreamWaitEvent(0, evJoin, 0);
    quantum_reg_kernel<<<BATCH / 4, 128>>>(W_post, b_post, out);
}